// round 5
// baseline (speedup 1.0000x reference)
#include <cuda_runtime.h>
#include <math.h>

// ---- problem constants (shapes fixed by the dataset) ----
#define NROWS      196608LL   // 4*3*128*128 z-rows of 128 floats
#define WARPS_PB   8
#define ROWS_PW    16
#define CHUNK      8          // float4 loads batched per thread before compute
#define NBLOCKS    1536       // NROWS / (WARPS_PB * ROWS_PW)

// Per-block partials: .x = sum(x^2), .y = 16 * sum over rows of (s0^2 + s1^2)
__device__ double2 g_part[NBLOCKS];
__device__ unsigned int g_ticket;   // zero-init; last block resets -> graph-replay safe

// One warp handles 16 consecutive z-rows (8 KB contiguous), in 2 chunks of 8.
// Loads for a chunk are batched into registers first (MLP ~ 8/thread), then the
// per-row reductions run on registers.
//
// Per-row reduction (6 shuffles instead of 10):
//   p0 = v.x+v.y+v.z+v.w (plain z-partial), p1 = v.x-v.y+v.z-v.w (alternating).
//   Exchange across the half-warp boundary (xor 16), then lo lanes reduce the
//   p0 half-sums while hi lanes reduce the p1 half-sums through xor 8,4,2,1.
//   All lanes end with t = (lane<16 ? s0_row : s1_row); accumulating t*t in
//   every lane yields warp-total 16*(s0^2+s1^2); the /16 folds into c2.
//
// Final loss = c0 + c1*E + c2*S  (host-precomputed coefficients; see kernel_launch).
__global__ void __launch_bounds__(256) spectral_kernel(const float4* __restrict__ x4,
                                                       float* __restrict__ out,
                                                       double c0, double c1, double c2) {
    const int lane = threadIdx.x & 31;
    const int wib  = threadIdx.x >> 5;
    const long long warp_id = (long long)blockIdx.x * WARPS_PB + wib;
    const float4* __restrict__ base = x4 + warp_id * (ROWS_PW * 32) + lane;

    float e  = 0.0f;   // per-lane sum of squares
    float ss = 0.0f;   // per-lane accumulated t^2 (warp total = 16*(s0^2+s1^2) per row)

    const bool lo_half = (lane < 16);

    #pragma unroll
    for (int c = 0; c < ROWS_PW / CHUNK; c++) {
        // ---- batched loads: 8 independent LDG.128 in flight ----
        float4 v[CHUNK];
        #pragma unroll
        for (int r = 0; r < CHUNK; r++)
            v[r] = base[(c * CHUNK + r) * 32];

        // ---- compute on registers ----
        #pragma unroll
        for (int r = 0; r < CHUNK; r++) {
            const float4 w = v[r];
            e += w.x * w.x + w.y * w.y + w.z * w.z + w.w * w.w;
            // z = 4*lane + {0,1,2,3} -> alternating signs +,-,+,-
            const float p0 = w.x + w.y + w.z + w.w;
            const float p1 = w.x - w.y + w.z - w.w;
            const float a  = __shfl_xor_sync(0xffffffffu, p0, 16);
            const float b  = __shfl_xor_sync(0xffffffffu, p1, 16);
            float t = lo_half ? (p0 + a) : (p1 + b);
            t += __shfl_xor_sync(0xffffffffu, t, 8);
            t += __shfl_xor_sync(0xffffffffu, t, 4);
            t += __shfl_xor_sync(0xffffffffu, t, 2);
            t += __shfl_xor_sync(0xffffffffu, t, 1);
            ss += t * t;
        }
    }

    // one warp-wide reduce of both accumulators
    #pragma unroll
    for (int o = 16; o > 0; o >>= 1) {
        e  += __shfl_xor_sync(0xffffffffu, e,  o);
        ss += __shfl_xor_sync(0xffffffffu, ss, o);
    }

    __shared__ float sh_e[WARPS_PB];
    __shared__ float sh_s[WARPS_PB];
    if (lane == 0) { sh_e[wib] = e; sh_s[wib] = ss; }
    __syncthreads();

    __shared__ bool is_last;
    if (threadIdx.x == 0) {
        double te = 0.0, ts = 0.0;
        #pragma unroll
        for (int i = 0; i < WARPS_PB; i++) { te += (double)sh_e[i]; ts += (double)sh_s[i]; }
        g_part[blockIdx.x] = make_double2(te, ts);
        __threadfence();
        unsigned int t = atomicAdd(&g_ticket, 1u);
        is_last = (t == NBLOCKS - 1);
    }
    __syncthreads();

    if (!is_last) return;

    // ---- last block: reduce all partials (hot in L2) and finalize ----
    const int tid = threadIdx.x;
    double te = 0.0, ts = 0.0;
    #pragma unroll
    for (int i = 0; i < NBLOCKS / 256; i++) {
        const double2 p = g_part[tid + i * 256];
        te += p.x; ts += p.y;
    }
    #pragma unroll
    for (int o = 16; o > 0; o >>= 1) {
        te += __shfl_xor_sync(0xffffffffu, te, o);
        ts += __shfl_xor_sync(0xffffffffu, ts, o);
    }
    __shared__ double fh_e[8];
    __shared__ double fh_s[8];
    if (lane == 0) { fh_e[wib] = te; fh_s[wib] = ts; }
    __syncthreads();

    if (tid == 0) {
        double E = 0.0, S = 0.0;
        #pragma unroll
        for (int i = 0; i < 8; i++) { E += fh_e[i]; S += fh_s[i]; }
        out[0] = (float)(c0 + c1 * E + c2 * S);
        g_ticket = 0;   // reset for next graph replay
    }
}

extern "C" void kernel_launch(void* const* d_in, const int* in_sizes, int n_in,
                              void* d_out, int out_size) {
    const float4* x4 = (const float4*)d_in[0];
    float* out = (float*)d_out;

    // ---- host-side constant folding ----
    // Derivation: k_mag uses NORMALIZED fft freqs (<= sqrt(3)/2); k_bins =
    // linspace(0,32,32) (k_max = min(128,128,65)//2 = 32) has spacing 32/31 >
    // sqrt(3)/2 => every point lands in bin 1:
    //   spectrum[1] = E_half/(128*128*65*4), all other bins zero.
    // E_half via Parseval: 0.5*(128^3*sum(x^2) + 128^2*sum(s0^2+s1^2)).
    // decay loss (spectrum[9:]==0): mean_{k=9..31}((k^{-5/3}/(9^{-5/3}+1e-8))^2),
    // data-independent. cascade loss = spectrum[1]/31.
    const double p = -5.0 / 3.0;
    const double denom = pow(9.0, p) + 1e-8;
    double acc = 0.0;
    for (int k = 9; k < 32; k++) {
        double en = pow((double)k, p) / denom;
        acc += en * en;
    }
    const double decay_loss = acc / 23.0;

    const double inv_npts = 1.0 / (128.0 * 128.0 * 65.0 * 4.0);
    const double c_casc   = 0.001 / 31.0;
    const double c0 = 0.01 * decay_loss;
    const double c1 = c_casc * 0.5 * 2097152.0 * inv_npts;          // * E = sum(x^2)
    const double c2 = c_casc * 0.5 * 16384.0   * inv_npts / 16.0;   // * S = 16*sum(s0^2+s1^2)

    spectral_kernel<<<NBLOCKS, 256>>>(x4, out, c0, c1, c2);
}